// round 9
// baseline (speedup 1.0000x reference)
#include <cuda_runtime.h>
#include <math.h>

#define BN 16
#define CN 256
#define NN 4096
#define KN 4
#define HN 512
#define SCALE 0.0625f   // 256^-0.5

// ---------------- scratch (device globals; no allocation) ----------------
__device__ float g_slots[BN*KN*CN];
__device__ float g_qkg  [BN*KN*CN];   // a[k][c] layout [c][k] handled in k_attn smem
__device__ float g_G    [BN*KN];
__device__ float g_off  [BN*KN];
__device__ float g_S    [BN*KN];
__device__ float g_U    [BN*KN];
__device__ float g_Araw [BN*KN*CN];
__device__ float g_mean [BN*NN];
__device__ float g_rstd [BN*NN];
__device__ float g_s1   [BN*KN*CN];
__device__ float g_h    [BN*KN*HN];
__device__ float g_z    [BN*KN];
// precomputed folded matrices/vectors
__device__ float g_M    [CN*CN];      // M[c'][c] = sum_d Wq[d][c']*Wk[d][c]
__device__ float g_N    [CN*CN];      // N[d][c]  = sum_e WuB[d][e]*Wv[e][c]
__device__ float g_bqk  [CN];         // sum_d bq[d]*Wk[d][c]
__device__ float g_wqbk [CN];         // sum_d Wq[d][c]*bk[d]
__device__ float g_wubbv[CN];         // sum_e WuB[d][e]*bv[e]
__device__ float g_bqbk;              // bq . bk

// 256-thread dual block reduction; red >= 16 floats.
__device__ __forceinline__ void blockReduce2(float& a, float& b, float* red) {
    #pragma unroll
    for (int o = 16; o; o >>= 1) {
        a += __shfl_down_sync(0xffffffffu, a, o);
        b += __shfl_down_sync(0xffffffffu, b, o);
    }
    int w = threadIdx.x >> 5;
    if ((threadIdx.x & 31) == 0) { red[w] = a; red[8 + w] = b; }
    __syncthreads();
    a = red[0]+red[1]+red[2]+red[3]+red[4]+red[5]+red[6]+red[7];
    b = red[8]+red[9]+red[10]+red[11]+red[12]+red[13]+red[14]+red[15];
    __syncthreads();
}

// ---------------- init (+ one block does vector precompute) ----------------
__global__ void k_init(const float* __restrict__ noise, const float* __restrict__ mu,
                       const float* __restrict__ lsig,
                       const float* __restrict__ Wq, const float* __restrict__ bq,
                       const float* __restrict__ Wk, const float* __restrict__ bk,
                       const float* __restrict__ Wu, const float* __restrict__ bv) {
    int r = blockIdx.x, c = threadIdx.x;
    if (r < BN*KN) {
        g_slots[r*CN + c] = mu[c] + expf(lsig[c]) * noise[r*CN + c];
        g_Araw[r*CN + c] = 0.f;
        if (c == 0) { g_S[r]=0.f; g_U[r]=0.f; g_G[r]=0.f; g_off[r]=0.f; g_z[r]=0.f; }
    } else {
        // vector precompute
        float acc1 = 0.f, acc2 = 0.f;
        #pragma unroll 8
        for (int d = 0; d < CN; d++) {
            acc1 += bq[d] * Wk[d*CN + c];       // bqk[c]
            acc2 += Wq[d*CN + c] * bk[d];       // wqbk[c]
        }
        g_bqk[c]  = acc1;
        g_wqbk[c] = acc2;
        float acc3 = 0.f;
        const float4* wrow = (const float4*)(Wu + c*512 + 256);
        const float4* bv4  = (const float4*)bv;
        #pragma unroll 8
        for (int e = 0; e < 64; e++) {
            float4 w = wrow[e], v = bv4[e];
            acc3 += w.x*v.x + w.y*v.y + w.z*v.z + w.w*v.w;
        }
        g_wubbv[c] = acc3;
        __shared__ float red[16];
        float p = bq[c]*bk[c], dummy = 0.f;
        blockReduce2(p, dummy, red);
        if (c == 0) g_bqbk = p;
    }
}

// ---------------- precompute M = Wq^T@Wk  and  N = WuB@Wv ------------------
// grid (16, 2): y==0 -> M (row group of 16), y==1 -> N. 256 threads.
__global__ void __launch_bounds__(256) k_pre(
    const float* __restrict__ Wq, const float* __restrict__ Wk,
    const float* __restrict__ Wu, const float* __restrict__ Wv)
{
    __shared__ float sA[64*16];
    int cg = blockIdx.x, which = blockIdx.y, tid = threadIdx.x;
    float acc[16];
    #pragma unroll
    for (int j = 0; j < 16; j++) acc[j] = 0.f;

    for (int dd = 0; dd < CN; dd += 64) {
        __syncthreads();
        #pragma unroll
        for (int t = 0; t < 4; t++) {
            int i = tid + t*256;
            int dl = i >> 4, j = i & 15;
            sA[i] = which == 0
                  ? Wq[(dd+dl)*CN + cg*16 + j]            // A[d][c'] column group
                  : Wu[(cg*16+j)*512 + 256 + dd + dl];    // WuB[row j][e]
        }
        __syncthreads();
        const float* B = which == 0 ? Wk : Wv;
        #pragma unroll 8
        for (int dl = 0; dl < 64; dl++) {
            float bvv = B[(dd+dl)*CN + tid];
            const float* arow = &sA[dl*16];
            #pragma unroll
            for (int j = 0; j < 16; j++) acc[j] += arow[j] * bvv;
        }
    }
    float* OUT = which == 0 ? g_M : g_N;
    #pragma unroll
    for (int j = 0; j < 16; j++) OUT[(cg*16+j)*CN + tid] = acc[j];
}

// ---------------- a = scale*(sv@M + bqk)*lig ; G, off  ---------------------
// grid (16, 4 chunks of 64 cols), 256 threads (4 slots x 64 cols)
__global__ void __launch_bounds__(256) k_a2(
    const float* __restrict__ lsg, const float* __restrict__ lsb,
    const float* __restrict__ lig, const float* __restrict__ lib)
{
    __shared__ __align__(16) float sv[4][256];
    __shared__ float red[16];
    int b = blockIdx.x, ch = blockIdx.y, tid = threadIdx.x;
    float lg = lsg[tid], lb = lsb[tid];
    #pragma unroll
    for (int k = 0; k < 4; k++) {
        float v = g_slots[(b*4+k)*CN + tid];
        float a = v, bb = v*v;
        blockReduce2(a, bb, red);
        float m = a * (1.0f/CN);
        float var = bb * (1.0f/CN) - m*m;
        float rs = rsqrtf(var + 1e-5f);
        sv[k][tid] = (v - m) * rs * lg + lb;
    }
    __syncthreads();

    int slot = tid >> 6, cl = tid & 63, c = ch*64 + cl;
    float acc = 0.f;
    #pragma unroll 8
    for (int d = 0; d < CN; d++) acc += sv[slot][d] * g_M[d*CN + c];
    float qk = acc + g_bqk[c];
    float av  = SCALE * qk * lig[c];
    g_qkg[(b*4+slot)*CN + c] = av;
    float offp = SCALE * (qk * lib[c] + sv[slot][c] * g_wqbk[c]);
    if (ch == 0 && cl == 0) offp += SCALE * g_bqbk;
    float Gs = av;
    #pragma unroll
    for (int o = 16; o; o >>= 1) {
        Gs   += __shfl_down_sync(0xffffffffu, Gs,   o);
        offp += __shfl_down_sync(0xffffffffu, offp, o);
    }
    if ((tid & 31) == 0) {
        atomicAdd(&g_G[b*4+slot], Gs);
        atomicAdd(&g_off[b*4+slot], offp);
    }
}

// ---------------- main attention pass ----------------
// grid (16 batches, 16 pixel-tiles of 256), 256 threads, 1 px/thread.
__global__ void __launch_bounds__(256) k_attn(const float* __restrict__ x, int first) {
    __shared__ __align__(16) float sa[1024];    // [c][k]: folded a
    __shared__ __align__(16) float st[4][256];  // t_k = attn*rs per pixel
    __shared__ float sc[8];                     // G[4], off[4]

    int b = blockIdx.x, t = blockIdx.y, tid = threadIdx.x;
    int n0 = t * 256;

    for (int i = tid; i < 1024; i += 256) {
        int k = i >> 8, c = i & 255;
        sa[c*4 + k] = g_qkg[b*1024 + i];
    }
    if (tid < 4) { sc[tid] = g_G[b*4 + tid]; sc[4+tid] = g_off[b*4 + tid]; }
    __syncthreads();

    // ---- phase 1: per-pixel dots over channels ----
    const float* xb = x + (size_t)b*CN*NN + n0 + tid;
    float d0=0,d1=0,d2=0,d3=0, sx=0, ss=0;
    if (first) {
        #pragma unroll 8
        for (int c = 0; c < CN; c++) {
            float v = xb[(size_t)c*NN];
            float4 a = *(const float4*)(sa + c*4);
            d0 += a.x*v; d1 += a.y*v; d2 += a.z*v; d3 += a.w*v;
            sx += v; ss += v*v;
        }
    } else {
        #pragma unroll 8
        for (int c = 0; c < CN; c++) {
            float v = xb[(size_t)c*NN];
            float4 a = *(const float4*)(sa + c*4);
            d0 += a.x*v; d1 += a.y*v; d2 += a.z*v; d3 += a.w*v;
        }
    }

    float m, rs;
    int n = n0 + tid;
    if (first) {
        m = sx * (1.0f/CN);
        float var = ss * (1.0f/CN) - m*m;
        rs = rsqrtf(var + 1e-5f);
        g_mean[b*NN + n] = m;
        g_rstd[b*NN + n] = rs;
    } else {
        m = g_mean[b*NN + n];
        rs = g_rstd[b*NN + n];
    }

    float l0 = rs*(d0 - m*sc[0]) + sc[4];
    float l1 = rs*(d1 - m*sc[1]) + sc[5];
    float l2 = rs*(d2 - m*sc[2]) + sc[6];
    float l3 = rs*(d3 - m*sc[3]) + sc[7];
    float M = fmaxf(fmaxf(l0,l1), fmaxf(l2,l3));
    float e0 = __expf(l0-M), e1 = __expf(l1-M), e2 = __expf(l2-M), e3 = __expf(l3-M);
    float iz = 1.0f / (e0+e1+e2+e3);
    float a0 = e0*iz, a1 = e1*iz, a2 = e2*iz, a3 = e3*iz;
    st[0][tid] = a0*rs; st[1][tid] = a1*rs;
    st[2][tid] = a2*rs; st[3][tid] = a3*rs;
    float rm = rs*m;
    float u0 = a0*rm, u1 = a1*rm, u2 = a2*rm, u3 = a3*rm;
    #pragma unroll
    for (int o = 16; o; o >>= 1) {
        a0 += __shfl_down_sync(0xffffffffu, a0, o);
        a1 += __shfl_down_sync(0xffffffffu, a1, o);
        a2 += __shfl_down_sync(0xffffffffu, a2, o);
        a3 += __shfl_down_sync(0xffffffffu, a3, o);
        u0 += __shfl_down_sync(0xffffffffu, u0, o);
        u1 += __shfl_down_sync(0xffffffffu, u1, o);
        u2 += __shfl_down_sync(0xffffffffu, u2, o);
        u3 += __shfl_down_sync(0xffffffffu, u3, o);
    }
    if ((tid & 31) == 0) {
        atomicAdd(&g_S[b*4+0], a0); atomicAdd(&g_S[b*4+1], a1);
        atomicAdd(&g_S[b*4+2], a2); atomicAdd(&g_S[b*4+3], a3);
        atomicAdd(&g_U[b*4+0], u0); atomicAdd(&g_U[b*4+1], u1);
        atomicAdd(&g_U[b*4+2], u2); atomicAdd(&g_U[b*4+3], u3);
    }
    __syncthreads();

    // ---- phase 2: Araw[k,c] += sum_p t_k[p]*x[c,p]; warp <-> 32 channels ----
    {
        int w = tid >> 5, lane = tid & 31;
        float4 tr[4][2];
        #pragma unroll
        for (int k = 0; k < 4; k++)
            #pragma unroll
            for (int j = 0; j < 2; j++)
                tr[k][j] = ((const float4*)st[k])[j*32 + lane];

        const float4* X4 = (const float4*)(x + (size_t)b*CN*NN + n0);
        #pragma unroll 2
        for (int cc = 0; cc < 32; cc++) {
            int c = w*32 + cc;
            const float4* xc = X4 + (size_t)c*(NN/4);
            float p0=0.f, p1=0.f, p2=0.f, p3=0.f;
            #pragma unroll
            for (int j = 0; j < 2; j++) {
                float4 xv = xc[j*32 + lane];
                p0 += xv.x*tr[0][j].x + xv.y*tr[0][j].y + xv.z*tr[0][j].z + xv.w*tr[0][j].w;
                p1 += xv.x*tr[1][j].x + xv.y*tr[1][j].y + xv.z*tr[1][j].z + xv.w*tr[1][j].w;
                p2 += xv.x*tr[2][j].x + xv.y*tr[2][j].y + xv.z*tr[2][j].z + xv.w*tr[2][j].w;
                p3 += xv.x*tr[3][j].x + xv.y*tr[3][j].y + xv.z*tr[3][j].z + xv.w*tr[3][j].w;
            }
            #pragma unroll
            for (int o = 16; o; o >>= 1) {
                p0 += __shfl_down_sync(0xffffffffu, p0, o);
                p1 += __shfl_down_sync(0xffffffffu, p1, o);
                p2 += __shfl_down_sync(0xffffffffu, p2, o);
                p3 += __shfl_down_sync(0xffffffffu, p3, o);
            }
            if (lane == 0) {
                atomicAdd(&g_Araw[(b*4+0)*CN + c], p0);
                atomicAdd(&g_Araw[(b*4+1)*CN + c], p1);
                atomicAdd(&g_Araw[(b*4+2)*CN + c], p2);
                atomicAdd(&g_Araw[(b*4+3)*CN + c], p3);
            }
        }
    }
}

// ---------------- fused update: s1 = prev@WuA^T + wx@N^T + folded biases ----
// grid (16, 4 chunks of 64 dims), 256 threads
__global__ void __launch_bounds__(256) k_u(
    const float* __restrict__ Wu, const float* __restrict__ bu,
    const float* __restrict__ lig, const float* __restrict__ lib)
{
    __shared__ __align__(16) float prev[4][256];
    __shared__ __align__(16) float wx  [4][256];
    __shared__ float sumw[4];
    int b = blockIdx.x, ch = blockIdx.y, tid = threadIdx.x;
    if (tid < 4) { float S = g_S[b*4+tid]; sumw[tid] = S / (S + 1e-8f); }
    float ligc = lig[tid], libc = lib[tid];
    #pragma unroll
    for (int k = 0; k < 4; k++) {
        float pv = g_slots[(b*4+k)*CN + tid];
        prev[k][tid] = pv;
        float S = g_S[b*4+k], U = g_U[b*4+k];
        wx[k][tid] = (ligc*(g_Araw[(b*4+k)*CN + tid] - U) + libc*S) / (S + 1e-8f);
    }
    __syncthreads();

    int warp = tid >> 5, lane = tid & 31;
    #pragma unroll
    for (int j = 0; j < 8; j++) {
        int dd = ch*64 + warp*8 + j;
        const float4* wa = (const float4*)(Wu + dd*512 + lane*8);       // WuA row
        const float4* wn = (const float4*)(g_N + dd*CN + lane*8);       // N row
        float4 a0 = wa[0], a1 = wa[1];
        float4 n0 = wn[0], n1 = wn[1];
        float acc[4];
        #pragma unroll
        for (int k = 0; k < 4; k++) {
            const float4* pk = (const float4*)&prev[k][lane*8];
            const float4* qk = (const float4*)&wx[k][lane*8];
            float4 p0 = pk[0], p1 = pk[1];
            float4 q0 = qk[0], q1 = qk[1];
            acc[k] = a0.x*p0.x + a0.y*p0.y + a0.z*p0.z + a0.w*p0.w
                   + a1.x*p1.x + a1.y*p1.y + a1.z*p1.z + a1.w*p1.w
                   + n0.x*q0.x + n0.y*q0.y + n0.z*q0.z + n0.w*q0.w
                   + n1.x*q1.x + n1.y*q1.y + n1.z*q1.z + n1.w*q1.w;
        }
        #pragma unroll
        for (int o = 16; o; o >>= 1)
            #pragma unroll
            for (int k = 0; k < 4; k++)
                acc[k] += __shfl_down_sync(0xffffffffu, acc[k], o);
        if (lane == 0) {
            float bud = bu[dd], wb = g_wubbv[dd];
            #pragma unroll
            for (int k = 0; k < 4; k++)
                g_s1[(b*4+k)*CN + dd] = acc[k] + bud + sumw[k]*wb + prev[k][dd];
        }
    }
}

// ---------------- h = gelu(LN(s1)@W1^T + b1)  (chunked) ---------------------
__global__ void __launch_bounds__(256) k_h(
    const float* __restrict__ W1, const float* __restrict__ b1,
    const float* __restrict__ lmg, const float* __restrict__ lmb)
{
    __shared__ __align__(16) float mln[4][256];
    __shared__ float red[16];
    int b = blockIdx.x, ch = blockIdx.y, tid = threadIdx.x;
    float lg = lmg[tid], lb = lmb[tid];
    #pragma unroll
    for (int k = 0; k < 4; k++) {
        float v = g_s1[(b*4+k)*CN + tid];
        float a = v, bb = v*v;
        blockReduce2(a, bb, red);
        float m = a * (1.0f/CN);
        float var = bb * (1.0f/CN) - m*m;
        float rs = rsqrtf(var + 1e-5f);
        mln[k][tid] = (v - m) * rs * lg + lb;
    }
    __syncthreads();

    int warp = tid >> 5, lane = tid & 31;
    #pragma unroll
    for (int j = 0; j < 8; j++) {
        int dd = ch*64 + warp*8 + j;
        const float4* w = (const float4*)(W1 + dd*CN + lane*8);
        float4 w0 = w[0], w1 = w[1];
        float acc[4];
        #pragma unroll
        for (int k = 0; k < 4; k++) {
            const float4* sk = (const float4*)&mln[k][lane*8];
            float4 a0 = sk[0], a1 = sk[1];
            acc[k] = w0.x*a0.x + w0.y*a0.y + w0.z*a0.z + w0.w*a0.w
                   + w1.x*a1.x + w1.y*a1.y + w1.z*a1.z + w1.w*a1.w;
        }
        #pragma unroll
        for (int o = 16; o; o >>= 1)
            #pragma unroll
            for (int k = 0; k < 4; k++)
                acc[k] += __shfl_down_sync(0xffffffffu, acc[k], o);
        if (lane == 0) {
            float bh = b1[dd];
            #pragma unroll
            for (int k = 0; k < 4; k++) {
                float h = acc[k] + bh;
                g_h[(b*4+k)*HN + dd] = h * normcdff(h);
            }
        }
    }
}

// ---------------- slots = s1 + h@W2^T + b2  (chunked); zero next accums -----
__global__ void __launch_bounds__(256) k_o(
    const float* __restrict__ W2, const float* __restrict__ b2,
    int final, float* __restrict__ out)
{
    __shared__ __align__(16) float hsm[4][512];
    int b = blockIdx.x, ch = blockIdx.y, tid = threadIdx.x;
    #pragma unroll
    for (int k = 0; k < 4; k++) {
        hsm[k][tid]       = g_h[(b*4+k)*HN + tid];
        hsm[k][256 + tid] = g_h[(b*4+k)*HN + 256 + tid];
    }
    __syncthreads();

    int warp = tid >> 5, lane = tid & 31;
    #pragma unroll
    for (int j = 0; j < 8; j++) {
        int dd = ch*64 + warp*8 + j;
        const float4* w = (const float4*)(W2 + dd*512 + lane*16);
        float4 w0 = w[0], w1 = w[1], w2 = w[2], w3 = w[3];
        float acc[4];
        #pragma unroll
        for (int k = 0; k < 4; k++) {
            const float4* sk = (const float4*)&hsm[k][lane*16];
            float4 a0 = sk[0], a1 = sk[1], a2 = sk[2], a3 = sk[3];
            acc[k] = w0.x*a0.x + w0.y*a0.y + w0.z*a0.z + w0.w*a0.w
                   + w1.x*a1.x + w1.y*a1.y + w1.z*a1.z + w1.w*a1.w
                   + w2.x*a2.x + w2.y*a2.y + w2.z*a2.z + w2.w*a2.w
                   + w3.x*a3.x + w3.y*a3.y + w3.z*a3.z + w3.w*a3.w;
        }
        #pragma unroll
        for (int o = 16; o; o >>= 1)
            #pragma unroll
            for (int k = 0; k < 4; k++)
                acc[k] += __shfl_down_sync(0xffffffffu, acc[k], o);
        if (lane == 0) {
            float b2d = b2[dd];
            #pragma unroll
            for (int k = 0; k < 4; k++) {
                float o_ = acc[k] + b2d + g_s1[(b*4+k)*CN + dd];
                g_slots[(b*4+k)*CN + dd] = o_;
                if (final) out[(b*4+k)*CN + dd] = o_;
            }
        }
    }

    int kk = tid >> 6, cl = tid & 63;
    g_Araw[(b*4+kk)*CN + ch*64 + cl] = 0.f;
    if (ch == 0 && tid < 4) {
        g_S[b*4+tid] = 0.f; g_U[b*4+tid] = 0.f;
        g_G[b*4+tid] = 0.f; g_off[b*4+tid] = 0.f;
    }
}

// ---------------- final head ----------------
__global__ void __launch_bounds__(256) k_f1(
    const float* __restrict__ We1, const float* __restrict__ be1,
    const float* __restrict__ We2)
{
    __shared__ __align__(16) float sl[4][256];
    int b = blockIdx.x, ch = blockIdx.y, tid = threadIdx.x;
    #pragma unroll
    for (int k = 0; k < 4; k++) sl[k][tid] = g_slots[(b*4+k)*CN + tid];
    __syncthreads();

    int warp = tid >> 5, lane = tid & 31;
    float zp[4] = {0,0,0,0};
    #pragma unroll
    for (int j = 0; j < 8; j++) {
        int dd = ch*64 + warp*8 + j;
        const float4* w = (const float4*)(We1 + dd*CN + lane*8);
        float4 w0 = w[0], w1 = w[1];
        float acc[4];
        #pragma unroll
        for (int k = 0; k < 4; k++) {
            const float4* sk = (const float4*)&sl[k][lane*8];
            float4 a0 = sk[0], a1 = sk[1];
            acc[k] = w0.x*a0.x + w0.y*a0.y + w0.z*a0.z + w0.w*a0.w
                   + w1.x*a1.x + w1.y*a1.y + w1.z*a1.z + w1.w*a1.w;
        }
        #pragma unroll
        for (int o = 16; o; o >>= 1)
            #pragma unroll
            for (int k = 0; k < 4; k++)
                acc[k] += __shfl_down_sync(0xffffffffu, acc[k], o);
        if (lane == 0) {
            float bed = be1[dd], wed = We2[dd];
            #pragma unroll
            for (int k = 0; k < 4; k++) {
                float e = acc[k] + bed;
                zp[k] += (e * normcdff(e)) * wed;
            }
        }
    }
    if (lane == 0) {
        #pragma unroll
        for (int k = 0; k < 4; k++) atomicAdd(&g_z[b*4+k], zp[k]);
    }
}

__global__ void k_f2(const float* __restrict__ be2, float* __restrict__ out, int out_size) {
    int r = threadIdx.x;
    if (out_size > BN*KN*CN) {
        float z = g_z[r] + be2[0];
        out[BN*KN*CN + r] = 1.0f / (1.0f + __expf(-z));
    }
}

// ---------------- launch ----------------
extern "C" void kernel_launch(void* const* d_in, const int* in_sizes, int n_in,
                              void* d_out, int out_size) {
    (void)in_sizes; (void)n_in;
    const float* x    = (const float*)d_in[0];
    const float* noise= (const float*)d_in[1];
    const float* mu   = (const float*)d_in[2];
    const float* lsig = (const float*)d_in[3];
    const float* lig  = (const float*)d_in[4];
    const float* lib  = (const float*)d_in[5];
    const float* lsg  = (const float*)d_in[6];
    const float* lsb  = (const float*)d_in[7];
    const float* lmg  = (const float*)d_in[8];
    const float* lmb  = (const float*)d_in[9];
    const float* Wq   = (const float*)d_in[10];
    const float* bq   = (const float*)d_in[11];
    const float* Wk   = (const float*)d_in[12];
    const float* bk   = (const float*)d_in[13];
    const float* Wv   = (const float*)d_in[14];
    const float* bv   = (const float*)d_in[15];
    const float* Wu   = (const float*)d_in[16];
    const float* bu   = (const float*)d_in[17];
    const float* W1   = (const float*)d_in[18];
    const float* b1   = (const float*)d_in[19];
    const float* W2   = (const float*)d_in[20];
    const float* b2   = (const float*)d_in[21];
    const float* We1  = (const float*)d_in[22];
    const float* be1  = (const float*)d_in[23];
    const float* We2  = (const float*)d_in[24];
    const float* be2  = (const float*)d_in[25];

    k_init<<<BN*KN + 1, CN>>>(noise, mu, lsig, Wq, bq, Wk, bk, Wu, bv);
    k_pre<<<dim3(16,2), 256>>>(Wq, Wk, Wu, Wv);
    for (int it = 0; it < 3; it++) {
        k_a2<<<dim3(16,4), 256>>>(lsg, lsb, lig, lib);
        k_attn<<<dim3(16,16), 256>>>(x, it == 0 ? 1 : 0);
        k_u <<<dim3(16,4), 256>>>(Wu, bu, lig, lib);
        k_h <<<dim3(16,8), 256>>>(W1, b1, lmg, lmb);
        k_o <<<dim3(16,4), 256>>>(W2, b2, it == 2 ? 1 : 0, (float*)d_out);
    }
    k_f1<<<dim3(16,2), 256>>>(We1, be1, We2);
    k_f2<<<1, 64>>>(be2, (float*)d_out, out_size);
}

// round 16
// speedup vs baseline: 1.0628x; 1.0628x over previous
#include <cuda_runtime.h>
#include <math.h>

#define BN 16
#define CN 256
#define NN 4096
#define KN 4
#define HN 512
#define SCALE 0.0625f   // 256^-0.5

// ---------------- scratch (device globals; no allocation) ----------------
__device__ float g_slots[BN*KN*CN];
__device__ float g_qkg  [BN*KN*CN];
__device__ float g_G    [BN*KN];
__device__ float g_off  [BN*KN];
__device__ float g_S    [BN*KN];
__device__ float g_U    [BN*KN];
__device__ float g_Araw [BN*KN*CN];
__device__ float g_mean [BN*NN];
__device__ float g_rstd [BN*NN];
__device__ float g_s1   [BN*KN*CN];
__device__ float g_h    [BN*KN*HN];
__device__ float g_z    [BN*KN];
// precomputed folded matrices/vectors
__device__ float g_M    [CN*CN];      // M[c'][c] = sum_d Wq[d][c']*Wk[d][c]
__device__ float g_N    [CN*CN];      // N[d][c]  = sum_e WuB[d][e]*Wv[e][c]
__device__ float g_bqk  [CN];
__device__ float g_wqbk [CN];
__device__ float g_wubbv[CN];
__device__ float g_bqbk;

// L2 evict_last via cache-hint policy (legal form on sm_103a for any width)
__device__ __forceinline__ unsigned long long mk_policy_el() {
    unsigned long long p;
    asm("createpolicy.fractional.L2::evict_last.b64 %0, 1.0;" : "=l"(p));
    return p;
}
__device__ __forceinline__ float ldg_el(const float* p, unsigned long long pol) {
    float v;
    asm volatile("ld.global.nc.L2::cache_hint.f32 %0, [%1], %2;"
                 : "=f"(v) : "l"(p), "l"(pol));
    return v;
}
__device__ __forceinline__ float4 ldg_el4(const float* p, unsigned long long pol) {
    float4 v;
    asm volatile("ld.global.nc.L2::cache_hint.v4.f32 {%0,%1,%2,%3}, [%4], %5;"
                 : "=f"(v.x), "=f"(v.y), "=f"(v.z), "=f"(v.w) : "l"(p), "l"(pol));
    return v;
}

// 256-thread dual block reduction; red >= 16 floats.
__device__ __forceinline__ void blockReduce2(float& a, float& b, float* red) {
    #pragma unroll
    for (int o = 16; o; o >>= 1) {
        a += __shfl_down_sync(0xffffffffu, a, o);
        b += __shfl_down_sync(0xffffffffu, b, o);
    }
    int w = threadIdx.x >> 5;
    if ((threadIdx.x & 31) == 0) { red[w] = a; red[8 + w] = b; }
    __syncthreads();
    a = red[0]+red[1]+red[2]+red[3]+red[4]+red[5]+red[6]+red[7];
    b = red[8]+red[9]+red[10]+red[11]+red[12]+red[13]+red[14]+red[15];
    __syncthreads();
}

// ---------------- init (+ one block does vector precompute) ----------------
__global__ void k_init(const float* __restrict__ noise, const float* __restrict__ mu,
                       const float* __restrict__ lsig,
                       const float* __restrict__ Wq, const float* __restrict__ bq,
                       const float* __restrict__ Wk, const float* __restrict__ bk,
                       const float* __restrict__ Wu, const float* __restrict__ bv) {
    int r = blockIdx.x, c = threadIdx.x;
    if (r < BN*KN) {
        g_slots[r*CN + c] = mu[c] + expf(lsig[c]) * noise[r*CN + c];
        g_Araw[r*CN + c] = 0.f;
        if (c == 0) { g_S[r]=0.f; g_U[r]=0.f; g_G[r]=0.f; g_off[r]=0.f; g_z[r]=0.f; }
    } else {
        float acc1 = 0.f, acc2 = 0.f;
        #pragma unroll 8
        for (int d = 0; d < CN; d++) {
            acc1 += bq[d] * Wk[d*CN + c];
            acc2 += Wq[d*CN + c] * bk[d];
        }
        g_bqk[c]  = acc1;
        g_wqbk[c] = acc2;
        float acc3 = 0.f;
        const float4* wrow = (const float4*)(Wu + c*512 + 256);
        const float4* bv4  = (const float4*)bv;
        #pragma unroll 8
        for (int e = 0; e < 64; e++) {
            float4 w = wrow[e], v = bv4[e];
            acc3 += w.x*v.x + w.y*v.y + w.z*v.z + w.w*v.w;
        }
        g_wubbv[c] = acc3;
        __shared__ float red[16];
        float p = bq[c]*bk[c], dummy = 0.f;
        blockReduce2(p, dummy, red);
        if (c == 0) g_bqbk = p;
    }
}

// ---------------- precompute M = Wq^T@Wk  and  N = WuB@Wv ------------------
__global__ void __launch_bounds__(256) k_pre(
    const float* __restrict__ Wq, const float* __restrict__ Wk,
    const float* __restrict__ Wu, const float* __restrict__ Wv)
{
    __shared__ float sA[64*16];
    int cg = blockIdx.x, which = blockIdx.y, tid = threadIdx.x;
    float acc[16];
    #pragma unroll
    for (int j = 0; j < 16; j++) acc[j] = 0.f;

    for (int dd = 0; dd < CN; dd += 64) {
        __syncthreads();
        #pragma unroll
        for (int t = 0; t < 4; t++) {
            int i = tid + t*256;
            int dl = i >> 4, j = i & 15;
            sA[i] = which == 0
                  ? Wq[(dd+dl)*CN + cg*16 + j]
                  : Wu[(cg*16+j)*512 + 256 + dd + dl];
        }
        __syncthreads();
        const float* B = which == 0 ? Wk : Wv;
        #pragma unroll 8
        for (int dl = 0; dl < 64; dl++) {
            float bvv = B[(dd+dl)*CN + tid];
            const float* arow = &sA[dl*16];
            #pragma unroll
            for (int j = 0; j < 16; j++) acc[j] += arow[j] * bvv;
        }
    }
    float* OUT = which == 0 ? g_M : g_N;
    #pragma unroll
    for (int j = 0; j < 16; j++) OUT[(cg*16+j)*CN + tid] = acc[j];
}

// ---------------- a = scale*(sv@M + bqk)*lig ; G, off  ---------------------
__global__ void __launch_bounds__(256) k_a2(
    const float* __restrict__ lsg, const float* __restrict__ lsb,
    const float* __restrict__ lig, const float* __restrict__ lib)
{
    __shared__ __align__(16) float sv[4][256];
    __shared__ float red[16];
    int b = blockIdx.x, ch = blockIdx.y, tid = threadIdx.x;
    float lg = lsg[tid], lb = lsb[tid];
    #pragma unroll
    for (int k = 0; k < 4; k++) {
        float v = g_slots[(b*4+k)*CN + tid];
        float a = v, bb = v*v;
        blockReduce2(a, bb, red);
        float m = a * (1.0f/CN);
        float var = bb * (1.0f/CN) - m*m;
        float rs = rsqrtf(var + 1e-5f);
        sv[k][tid] = (v - m) * rs * lg + lb;
    }
    __syncthreads();

    int slot = tid >> 6, cl = tid & 63, c = ch*64 + cl;
    float acc = 0.f;
    #pragma unroll 8
    for (int d = 0; d < CN; d++) acc += sv[slot][d] * g_M[d*CN + c];
    float qk = acc + g_bqk[c];
    float av  = SCALE * qk * lig[c];
    g_qkg[(b*4+slot)*CN + c] = av;
    float offp = SCALE * (qk * lib[c] + sv[slot][c] * g_wqbk[c]);
    if (ch == 0 && cl == 0) offp += SCALE * g_bqbk;
    float Gs = av;
    #pragma unroll
    for (int o = 16; o; o >>= 1) {
        Gs   += __shfl_down_sync(0xffffffffu, Gs,   o);
        offp += __shfl_down_sync(0xffffffffu, offp, o);
    }
    if ((tid & 31) == 0) {
        atomicAdd(&g_G[b*4+slot], Gs);
        atomicAdd(&g_off[b*4+slot], offp);
    }
}

// ---------------- main attention pass ----------------
// grid (16 batches, 32 pixel-tiles of 128), 128 threads, 1 px/thread.
__global__ void __launch_bounds__(128) k_attn(const float* __restrict__ x, int first) {
    __shared__ __align__(16) float sa[1024];    // [c][k]: folded a
    __shared__ __align__(16) float st[4][128];  // t_k = attn*rs per pixel
    __shared__ float sc[8];                     // G[4], off[4]

    int b = blockIdx.x, t = blockIdx.y, tid = threadIdx.x;
    int n0 = t * 128;
    unsigned long long pol = mk_policy_el();

    for (int i = tid; i < 1024; i += 128) {
        int k = i >> 8, c = i & 255;
        sa[c*4 + k] = g_qkg[b*1024 + i];
    }
    if (tid < 4) { sc[tid] = g_G[b*4 + tid]; sc[4+tid] = g_off[b*4 + tid]; }
    __syncthreads();

    // ---- phase 1: per-pixel dots over channels (evict_last, deep unroll) ----
    const float* xb = x + (size_t)b*CN*NN + n0 + tid;
    float d0=0,d1=0,d2=0,d3=0, sx=0, ss=0;
    if (first) {
        #pragma unroll 16
        for (int c = 0; c < CN; c++) {
            float v = ldg_el(xb + (size_t)c*NN, pol);
            float4 a = *(const float4*)(sa + c*4);
            d0 += a.x*v; d1 += a.y*v; d2 += a.z*v; d3 += a.w*v;
            sx += v; ss += v*v;
        }
    } else {
        #pragma unroll 16
        for (int c = 0; c < CN; c++) {
            float v = ldg_el(xb + (size_t)c*NN, pol);
            float4 a = *(const float4*)(sa + c*4);
            d0 += a.x*v; d1 += a.y*v; d2 += a.z*v; d3 += a.w*v;
        }
    }

    float m, rs;
    int n = n0 + tid;
    if (first) {
        m = sx * (1.0f/CN);
        float var = ss * (1.0f/CN) - m*m;
        rs = rsqrtf(var + 1e-5f);
        g_mean[b*NN + n] = m;
        g_rstd[b*NN + n] = rs;
    } else {
        m = g_mean[b*NN + n];
        rs = g_rstd[b*NN + n];
    }

    float l0 = rs*(d0 - m*sc[0]) + sc[4];
    float l1 = rs*(d1 - m*sc[1]) + sc[5];
    float l2 = rs*(d2 - m*sc[2]) + sc[6];
    float l3 = rs*(d3 - m*sc[3]) + sc[7];
    float M = fmaxf(fmaxf(l0,l1), fmaxf(l2,l3));
    float e0 = __expf(l0-M), e1 = __expf(l1-M), e2 = __expf(l2-M), e3 = __expf(l3-M);
    float iz = 1.0f / (e0+e1+e2+e3);
    float a0 = e0*iz, a1 = e1*iz, a2 = e2*iz, a3 = e3*iz;
    st[0][tid] = a0*rs; st[1][tid] = a1*rs;
    st[2][tid] = a2*rs; st[3][tid] = a3*rs;
    float rm = rs*m;
    float u0 = a0*rm, u1 = a1*rm, u2 = a2*rm, u3 = a3*rm;
    #pragma unroll
    for (int o = 16; o; o >>= 1) {
        a0 += __shfl_down_sync(0xffffffffu, a0, o);
        a1 += __shfl_down_sync(0xffffffffu, a1, o);
        a2 += __shfl_down_sync(0xffffffffu, a2, o);
        a3 += __shfl_down_sync(0xffffffffu, a3, o);
        u0 += __shfl_down_sync(0xffffffffu, u0, o);
        u1 += __shfl_down_sync(0xffffffffu, u1, o);
        u2 += __shfl_down_sync(0xffffffffu, u2, o);
        u3 += __shfl_down_sync(0xffffffffu, u3, o);
    }
    if ((tid & 31) == 0) {
        atomicAdd(&g_S[b*4+0], a0); atomicAdd(&g_S[b*4+1], a1);
        atomicAdd(&g_S[b*4+2], a2); atomicAdd(&g_S[b*4+3], a3);
        atomicAdd(&g_U[b*4+0], u0); atomicAdd(&g_U[b*4+1], u1);
        atomicAdd(&g_U[b*4+2], u2); atomicAdd(&g_U[b*4+3], u3);
    }
    __syncthreads();

    // ---- phase 2: Araw[k,c] += sum_p t_k[p]*x[c,p] ----
    // Warp handles 64 channels, 4 at a time: sub = lane>>3 selects channel,
    // 8-lane groups (j = lane&7) split the 128 pixels.
    {
        int w = tid >> 5, lane = tid & 31;
        int sub = lane >> 3, j = lane & 7;

        float4 tr[4][4];
        #pragma unroll
        for (int k = 0; k < 4; k++)
            #pragma unroll
            for (int it = 0; it < 4; it++)
                tr[k][it] = *(const float4*)&st[k][it*32 + j*4];

        const float* xbase = x + (size_t)b*CN*NN + n0;
        #pragma unroll 2
        for (int cg = 0; cg < 16; cg++) {
            int c = w*64 + cg*4 + sub;
            const float* xc = xbase + (size_t)c*NN;
            float p0=0.f, p1=0.f, p2=0.f, p3=0.f;
            #pragma unroll
            for (int it = 0; it < 4; it++) {
                float4 xv = ldg_el4(xc + it*32 + j*4, pol);
                p0 += xv.x*tr[0][it].x + xv.y*tr[0][it].y + xv.z*tr[0][it].z + xv.w*tr[0][it].w;
                p1 += xv.x*tr[1][it].x + xv.y*tr[1][it].y + xv.z*tr[1][it].z + xv.w*tr[1][it].w;
                p2 += xv.x*tr[2][it].x + xv.y*tr[2][it].y + xv.z*tr[2][it].z + xv.w*tr[2][it].w;
                p3 += xv.x*tr[3][it].x + xv.y*tr[3][it].y + xv.z*tr[3][it].z + xv.w*tr[3][it].w;
            }
            #pragma unroll
            for (int o = 4; o; o >>= 1) {
                p0 += __shfl_down_sync(0xffffffffu, p0, o);
                p1 += __shfl_down_sync(0xffffffffu, p1, o);
                p2 += __shfl_down_sync(0xffffffffu, p2, o);
                p3 += __shfl_down_sync(0xffffffffu, p3, o);
            }
            if (j == 0) {
                atomicAdd(&g_Araw[(b*4+0)*CN + c], p0);
                atomicAdd(&g_Araw[(b*4+1)*CN + c], p1);
                atomicAdd(&g_Araw[(b*4+2)*CN + c], p2);
                atomicAdd(&g_Araw[(b*4+3)*CN + c], p3);
            }
        }
    }
}

// ---------------- fused update: s1 = prev@WuA^T + wx@N^T + folded biases ----
__global__ void __launch_bounds__(256) k_u(
    const float* __restrict__ Wu, const float* __restrict__ bu,
    const float* __restrict__ lig, const float* __restrict__ lib)
{
    __shared__ __align__(16) float prev[4][256];
    __shared__ __align__(16) float wx  [4][256];
    __shared__ float sumw[4];
    int b = blockIdx.x, ch = blockIdx.y, tid = threadIdx.x;
    if (tid < 4) { float S = g_S[b*4+tid]; sumw[tid] = S / (S + 1e-8f); }
    float ligc = lig[tid], libc = lib[tid];
    #pragma unroll
    for (int k = 0; k < 4; k++) {
        float pv = g_slots[(b*4+k)*CN + tid];
        prev[k][tid] = pv;
        float S = g_S[b*4+k], U = g_U[b*4+k];
        wx[k][tid] = (ligc*(g_Araw[(b*4+k)*CN + tid] - U) + libc*S) / (S + 1e-8f);
    }
    __syncthreads();

    int warp = tid >> 5, lane = tid & 31;
    #pragma unroll
    for (int j = 0; j < 8; j++) {
        int dd = ch*64 + warp*8 + j;
        const float4* wa = (const float4*)(Wu + dd*512 + lane*8);
        const float4* wn = (const float4*)(g_N + dd*CN + lane*8);
        float4 a0 = wa[0], a1 = wa[1];
        float4 n0 = wn[0], n1 = wn[1];
        float acc[4];
        #pragma unroll
        for (int k = 0; k < 4; k++) {
            const float4* pk = (const float4*)&prev[k][lane*8];
            const float4* qk = (const float4*)&wx[k][lane*8];
            float4 p0 = pk[0], p1 = pk[1];
            float4 q0 = qk[0], q1 = qk[1];
            acc[k] = a0.x*p0.x + a0.y*p0.y + a0.z*p0.z + a0.w*p0.w
                   + a1.x*p1.x + a1.y*p1.y + a1.z*p1.z + a1.w*p1.w
                   + n0.x*q0.x + n0.y*q0.y + n0.z*q0.z + n0.w*q0.w
                   + n1.x*q1.x + n1.y*q1.y + n1.z*q1.z + n1.w*q1.w;
        }
        #pragma unroll
        for (int o = 16; o; o >>= 1)
            #pragma unroll
            for (int k = 0; k < 4; k++)
                acc[k] += __shfl_down_sync(0xffffffffu, acc[k], o);
        if (lane == 0) {
            float bud = bu[dd], wb = g_wubbv[dd];
            #pragma unroll
            for (int k = 0; k < 4; k++)
                g_s1[(b*4+k)*CN + dd] = acc[k] + bud + sumw[k]*wb + prev[k][dd];
        }
    }
}

// ---------------- h = gelu(LN(s1)@W1^T + b1)  (chunked) ---------------------
__global__ void __launch_bounds__(256) k_h(
    const float* __restrict__ W1, const float* __restrict__ b1,
    const float* __restrict__ lmg, const float* __restrict__ lmb)
{
    __shared__ __align__(16) float mln[4][256];
    __shared__ float red[16];
    int b = blockIdx.x, ch = blockIdx.y, tid = threadIdx.x;
    float lg = lmg[tid], lb = lmb[tid];
    #pragma unroll
    for (int k = 0; k < 4; k++) {
        float v = g_s1[(b*4+k)*CN + tid];
        float a = v, bb = v*v;
        blockReduce2(a, bb, red);
        float m = a * (1.0f/CN);
        float var = bb * (1.0f/CN) - m*m;
        float rs = rsqrtf(var + 1e-5f);
        mln[k][tid] = (v - m) * rs * lg + lb;
    }
    __syncthreads();

    int warp = tid >> 5, lane = tid & 31;
    #pragma unroll
    for (int j = 0; j < 8; j++) {
        int dd = ch*64 + warp*8 + j;
        const float4* w = (const float4*)(W1 + dd*CN + lane*8);
        float4 w0 = w[0], w1 = w[1];
        float acc[4];
        #pragma unroll
        for (int k = 0; k < 4; k++) {
            const float4* sk = (const float4*)&mln[k][lane*8];
            float4 a0 = sk[0], a1 = sk[1];
            acc[k] = w0.x*a0.x + w0.y*a0.y + w0.z*a0.z + w0.w*a0.w
                   + w1.x*a1.x + w1.y*a1.y + w1.z*a1.z + w1.w*a1.w;
        }
        #pragma unroll
        for (int o = 16; o; o >>= 1)
            #pragma unroll
            for (int k = 0; k < 4; k++)
                acc[k] += __shfl_down_sync(0xffffffffu, acc[k], o);
        if (lane == 0) {
            float bh = b1[dd];
            #pragma unroll
            for (int k = 0; k < 4; k++) {
                float h = acc[k] + bh;
                g_h[(b*4+k)*HN + dd] = h * normcdff(h);
            }
        }
    }
}

// ---------------- slots = s1 + h@W2^T + b2  (chunked); zero next accums -----
__global__ void __launch_bounds__(256) k_o(
    const float* __restrict__ W2, const float* __restrict__ b2,
    int final, float* __restrict__ out)
{
    __shared__ __align__(16) float hsm[4][512];
    int b = blockIdx.x, ch = blockIdx.y, tid = threadIdx.x;
    #pragma unroll
    for (int k = 0; k < 4; k++) {
        hsm[k][tid]       = g_h[(b*4+k)*HN + tid];
        hsm[k][256 + tid] = g_h[(b*4+k)*HN + 256 + tid];
    }
    __syncthreads();

    int warp = tid >> 5, lane = tid & 31;
    #pragma unroll
    for (int j = 0; j < 8; j++) {
        int dd = ch*64 + warp*8 + j;
        const float4* w = (const float4*)(W2 + dd*512 + lane*16);
        float4 w0 = w[0], w1 = w[1], w2 = w[2], w3 = w[3];
        float acc[4];
        #pragma unroll
        for (int k = 0; k < 4; k++) {
            const float4* sk = (const float4*)&hsm[k][lane*16];
            float4 a0 = sk[0], a1 = sk[1], a2 = sk[2], a3 = sk[3];
            acc[k] = w0.x*a0.x + w0.y*a0.y + w0.z*a0.z + w0.w*a0.w
                   + w1.x*a1.x + w1.y*a1.y + w1.z*a1.z + w1.w*a1.w
                   + w2.x*a2.x + w2.y*a2.y + w2.z*a2.z + w2.w*a2.w
                   + w3.x*a3.x + w3.y*a3.y + w3.z*a3.z + w3.w*a3.w;
        }
        #pragma unroll
        for (int o = 16; o; o >>= 1)
            #pragma unroll
            for (int k = 0; k < 4; k++)
                acc[k] += __shfl_down_sync(0xffffffffu, acc[k], o);
        if (lane == 0) {
            float b2d = b2[dd];
            #pragma unroll
            for (int k = 0; k < 4; k++) {
                float o_ = acc[k] + b2d + g_s1[(b*4+k)*CN + dd];
                g_slots[(b*4+k)*CN + dd] = o_;
                if (final) out[(b*4+k)*CN + dd] = o_;
            }
        }
    }

    int kk = tid >> 6, cl = tid & 63;
    g_Araw[(b*4+kk)*CN + ch*64 + cl] = 0.f;
    if (ch == 0 && tid < 4) {
        g_S[b*4+tid] = 0.f; g_U[b*4+tid] = 0.f;
        g_G[b*4+tid] = 0.f; g_off[b*4+tid] = 0.f;
    }
}

// ---------------- final head ----------------
__global__ void __launch_bounds__(256) k_f1(
    const float* __restrict__ We1, const float* __restrict__ be1,
    const float* __restrict__ We2)
{
    __shared__ __align__(16) float sl[4][256];
    int b = blockIdx.x, ch = blockIdx.y, tid = threadIdx.x;
    #pragma unroll
    for (int k = 0; k < 4; k++) sl[k][tid] = g_slots[(b*4+k)*CN + tid];
    __syncthreads();

    int warp = tid >> 5, lane = tid & 31;
    float zp[4] = {0,0,0,0};
    #pragma unroll
    for (int j = 0; j < 8; j++) {
        int dd = ch*64 + warp*8 + j;
        const float4* w = (const float4*)(We1 + dd*CN + lane*8);
        float4 w0 = w[0], w1 = w[1];
        float acc[4];
        #pragma unroll
        for (int k = 0; k < 4; k++) {
            const float4* sk = (const float4*)&sl[k][lane*8];
            float4 a0 = sk[0], a1 = sk[1];
            acc[k] = w0.x*a0.x + w0.y*a0.y + w0.z*a0.z + w0.w*a0.w
                   + w1.x*a1.x + w1.y*a1.y + w1.z*a1.z + w1.w*a1.w;
        }
        #pragma unroll
        for (int o = 16; o; o >>= 1)
            #pragma unroll
            for (int k = 0; k < 4; k++)
                acc[k] += __shfl_down_sync(0xffffffffu, acc[k], o);
        if (lane == 0) {
            float bed = be1[dd], wed = We2[dd];
            #pragma unroll
            for (int k = 0; k < 4; k++) {
                float e = acc[k] + bed;
                zp[k] += (e * normcdff(e)) * wed;
            }
        }
    }
    if (lane == 0) {
        #pragma unroll
        for (int k = 0; k < 4; k++) atomicAdd(&g_z[b*4+k], zp[k]);
    }
}

__global__ void k_f2(const float* __restrict__ be2, float* __restrict__ out, int out_size) {
    int r = threadIdx.x;
    if (out_size > BN*KN*CN) {
        float z = g_z[r] + be2[0];
        out[BN*KN*CN + r] = 1.0f / (1.0f + __expf(-z));
    }
}

// ---------------- launch ----------------
extern "C" void kernel_launch(void* const* d_in, const int* in_sizes, int n_in,
                              void* d_out, int out_size) {
    (void)in_sizes; (void)n_in;
    const float* x    = (const float*)d_in[0];
    const float* noise= (const float*)d_in[1];
    const float* mu   = (const float*)d_in[2];
    const float* lsig = (const float*)d_in[3];
    const float* lig  = (const float*)d_in[4];
    const float* lib  = (const float*)d_in[5];
    const float* lsg  = (const float*)d_in[6];
    const float* lsb  = (const float*)d_in[7];
    const float* lmg  = (const float*)d_in[8];
    const float* lmb  = (const float*)d_in[9];
    const float* Wq   = (const float*)d_in[10];
    const float* bq   = (const float*)d_in[11];
    const float* Wk   = (const float*)d_in[12];
    const float* bk   = (const float*)d_in[13];
    const float* Wv   = (const float*)d_in[14];
    const float* bv   = (const float*)d_in[15];
    const float* Wu   = (const float*)d_in[16];
    const float* bu   = (const float*)d_in[17];
    const float* W1   = (const float*)d_in[18];
    const float* b1   = (const float*)d_in[19];
    const float* W2   = (const float*)d_in[20];
    const float* b2   = (const float*)d_in[21];
    const float* We1  = (const float*)d_in[22];
    const float* be1  = (const float*)d_in[23];
    const float* We2  = (const float*)d_in[24];
    const float* be2  = (const float*)d_in[25];

    k_init<<<BN*KN + 1, CN>>>(noise, mu, lsig, Wq, bq, Wk, bk, Wu, bv);
    k_pre<<<dim3(16,2), 256>>>(Wq, Wk, Wu, Wv);
    for (int it = 0; it < 3; it++) {
        k_a2<<<dim3(16,4), 256>>>(lsg, lsb, lig, lib);
        k_attn<<<dim3(16,32), 128>>>(x, it == 0 ? 1 : 0);
        k_u <<<dim3(16,4), 256>>>(Wu, bu, lig, lib);
        k_h <<<dim3(16,8), 256>>>(W1, b1, lmg, lmb);
        k_o <<<dim3(16,4), 256>>>(W2, b2, it == 2 ? 1 : 0, (float*)d_out);
    }
    k_f1<<<dim3(16,2), 256>>>(We1, be1, We2);
    k_f2<<<1, 64>>>(be2, (float*)d_out, out_size);
}